// round 7
// baseline (speedup 1.0000x reference)
#include <cuda_runtime.h>
#include <math.h>
#include <limits.h>

#define NIMG 4
#define NPRI 3106
#define NCLS 20      // classes 1..20 (background excluded)
#define NTOT 21
#define NPAD 4096    // max pow2 bound for sort arrays
#define TOPK 200

#define MIN_SCORE 0.05f
#define MAX_OVERLAP 0.45f

#define NMS_NT 512
#define NWARPS (NMS_NT / 32)

// ---------------- device scratch (no allocations allowed) ----------------
__device__ float  g_cls[NIMG][NCLS][NPRI];      // class-major probs
__device__ float4 g_box[NIMG][NPRI];            // decoded boxes x1,y1,x2,y2
__device__ float  g_candScore[NIMG][NCLS][TOPK];
__device__ float4 g_candBox[NIMG][NCLS][TOPK];
__device__ int    g_candCnt[NIMG][NCLS];

// Fast double-precision exp (Cody-Waite + deg-12 Taylor, rel err ~2^-52).
__device__ __forceinline__ float exp_df(float xf)
{
    double x = (double)xf;
    float nf = rintf(xf * 1.4426950408889634f);
    double n = (double)nf;
    double r = fma(n, -0.6931471805599453, x);
    r = fma(n, -2.3190468138462996e-17, r);
    double p = 2.08767569878681e-09;
    p = fma(p, r, 2.505210838544172e-08);
    p = fma(p, r, 2.755731922398589e-07);
    p = fma(p, r, 2.755731922398589e-06);
    p = fma(p, r, 2.480158730158730e-05);
    p = fma(p, r, 1.984126984126984e-04);
    p = fma(p, r, 1.388888888888889e-03);
    p = fma(p, r, 8.333333333333333e-03);
    p = fma(p, r, 4.166666666666666e-02);
    p = fma(p, r, 1.666666666666667e-01);
    p = fma(p, r, 0.5);
    p = fma(p, r, 1.0);
    p = fma(p, r, 1.0);
    long long ni = (long long)nf;
    double sc = __longlong_as_double((ni + 1023LL) << 52);
    return (float)(p * sc);
}

// ---------------- kernel 1: softmax + box decode (thread per row) ----------------
__global__ void softmax_decode_kernel(const float* __restrict__ locs,
                                      const float* __restrict__ scores,
                                      const float* __restrict__ priors)
{
    int row = blockIdx.x * blockDim.x + threadIdx.x;
    if (row >= NIMG * NPRI) return;
    int img = row / NPRI;
    int p   = row - img * NPRI;

    const float* s = scores + (size_t)row * NTOT;
    float m = s[0];
    #pragma unroll
    for (int c = 1; c < NTOT; c++) m = fmaxf(m, s[c]);

    float e[NTOT];
    double dsum = 0.0;
    #pragma unroll
    for (int c = 0; c < NTOT; c++) {
        e[c] = exp_df(s[c] - m);
        dsum += (double)e[c];
    }
    float fsum = (float)dsum;
    #pragma unroll
    for (int c = 1; c < NTOT; c++)
        g_cls[img][c - 1][p] = __fdiv_rn(e[c], fsum);

    const float* l  = locs + (size_t)row * 4;
    const float* pr = priors + (size_t)p * 4;
    float cx = __fdiv_rn(l[0] * pr[2], 10.0f) + pr[0];
    float cy = __fdiv_rn(l[1] * pr[3], 10.0f) + pr[1];
    float w  = exp_df(__fdiv_rn(l[2], 5.0f)) * pr[2];
    float h  = exp_df(__fdiv_rn(l[3], 5.0f)) * pr[3];
    float4 b;
    b.x = cx - __fdiv_rn(w, 2.0f);
    b.y = cy - __fdiv_rn(h, 2.0f);
    b.z = cx + __fdiv_rn(w, 2.0f);
    b.w = cy + __fdiv_rn(h, 2.0f);
    g_box[img][p] = b;
}

// IoU with precomputed areas; float semantics identical to reference
__device__ __forceinline__ float iou_pa(float4 a, float aA, float4 b, float aB)
{
    float dx = fminf(a.z, b.z) - fmaxf(a.x, b.x);
    float dy = fminf(a.w, b.w) - fmaxf(a.y, b.y);
    float inter = fmaxf(dx, 0.0f) * fmaxf(dy, 0.0f);
    return __fdiv_rn(inter, aA + aB - inter);
}

// ---------------- kernel 2: per-(image,class) greedy NMS ----------------
// Dynamic shared layout:
//   [0, 16384)      float  skey[NPAD]
//   [16384, 32768)  int    sidx[NPAD]   (aliased by float sarea after gather)
//   [32768, 82464)  float4 sbox[NPRI]
#define SMEM_NMS_BYTES 82464

__global__ void __launch_bounds__(NMS_NT, 1)
nms_kernel()
{
    extern __shared__ char sm[];
    float*  skey  = (float*)(sm);
    int*    sidx  = (int*)(sm + NPAD * 4);
    float*  sarea = (float*)(sm + NPAD * 4);   // aliases sidx (dead after gather)
    float4* sbox  = (float4*)(sm + NPAD * 8);
    __shared__ int      s_wcnt[NWARPS];
    __shared__ unsigned s_keptmask;
    __shared__ float4   s_kbox[32];
    __shared__ float    s_karea[32];

    int img  = blockIdx.x / NCLS;
    int c    = blockIdx.x % NCLS;
    int tid  = threadIdx.x;
    int wid  = tid >> 5;
    int lane = tid & 31;
    unsigned lmask = (1u << lane) - 1u;

    // ---- Phase A: stable compaction of valid entries (order-preserving) ----
    int base = 0;
    for (int bp = 0; bp < NPRI; bp += NMS_NT) {
        int p = bp + tid;
        float sc = (p < NPRI) ? g_cls[img][c][p] : 0.0f;
        bool ok = (p < NPRI) && (sc > MIN_SCORE);
        unsigned b = __ballot_sync(0xffffffffu, ok);
        if (lane == 0) s_wcnt[wid] = __popc(b);
        __syncthreads();
        int wpre = 0, wsum = 0;
        #pragma unroll
        for (int w = 0; w < NWARPS; w++) {
            int cnt = s_wcnt[w];
            if (w < wid) wpre += cnt;
            wsum += cnt;
        }
        int rank = base + wpre + __popc(b & lmask);
        if (ok) { skey[rank] = sc; sidx[rank] = p; }
        base += wsum;
        __syncthreads();
    }
    int nvalid = base;

    int keptTotal = 0;

    if (nvalid > 0) {
        int npow = 32;
        while (npow < nvalid) npow <<= 1;
        for (int t = nvalid + tid; t < npow; t += NMS_NT) {
            skey[t] = -INFINITY;
            sidx[t] = NPRI + t;
        }
        __syncthreads();

        // ---- Phase B: bitonic sort (score desc, index asc) ----
        for (int k = 2; k <= npow; k <<= 1) {
            for (int j = k >> 1; j > 0; j >>= 1) {
                for (int t = tid; t < npow; t += NMS_NT) {
                    int l = t ^ j;
                    if (l > t) {
                        float ka = skey[t], kb = skey[l];
                        int   ia = sidx[t], ib = sidx[l];
                        bool asc = ((t & k) == 0);
                        bool beforeBA = (kb > ka) || (kb == ka && ib < ia);
                        if (beforeBA == asc) {
                            skey[t] = kb; skey[l] = ka;
                            sidx[t] = ib; sidx[l] = ia;
                        }
                    }
                }
                __syncthreads();
            }
        }

        // ---- Phase C: gather boxes + compute areas (sarea overwrites sidx) ----
        for (int i = tid; i < nvalid; i += NMS_NT) {
            float4 b = g_box[img][sidx[i]];   // read sidx[i] BEFORE aliased write
            sbox[i]  = b;
            sarea[i] = (b.z - b.x) * (b.w - b.y);
        }
        __syncthreads();

        // ---- Phase D: chunked greedy, suppress only vs KEPT boxes ----
        int nrem = nvalid;
        while (nrem > 0 && keptTotal < TOPK) {
            int m = min(32, nrem);

            if (wid == 0) {
                int li = (lane < m) ? lane : (m - 1);
                float4 bown = sbox[li];
                float  aown = sarea[li];
                unsigned row = 0;   // bits j>lane that I overlap
                for (int j = 1; j < m; j++) {
                    float4 bj = sbox[j];      // LDS broadcast
                    float  aj = sarea[j];
                    if (j > lane && iou_pa(bown, aown, bj, aj) > MAX_OVERLAP)
                        row |= 1u << j;
                }
                unsigned unres = (m == 32) ? 0xffffffffu : ((1u << m) - 1u);
                unsigned kept = 0;
                while (unres) {
                    int i = __ffs(unres) - 1;
                    kept |= 1u << i;
                    unsigned ri = __shfl_sync(0xffffffffu, row, i);
                    unres &= ~(ri | (1u << i));
                }
                bool mykept = (lane < m) && ((kept >> lane) & 1u);
                int myrank = __popc(kept & lmask);
                if (mykept) {
                    int slot = keptTotal + myrank;
                    if (slot < TOPK) {
                        g_candScore[img][c][slot] = skey[lane];
                        g_candBox[img][c][slot]   = bown;
                    }
                    s_kbox[myrank]  = bown;
                    s_karea[myrank] = aown;
                }
                if (lane == 0) s_keptmask = kept;
            }
            __syncthreads();

            int nk = __popc(s_keptmask);
            keptTotal += nk;
            if (keptTotal >= TOPK) break;
            if (nrem <= m) { nrem = 0; break; }

            // fused suppress (vs nk kept boxes, early exit) + stable compact
            int newbase = 0;
            for (int start = m; start < nrem; start += NMS_NT) {
                int j = start + tid;
                bool ok = (j < nrem);
                float key = 0.0f, ar = 0.0f; float4 bx;
                if (ok) {
                    key = skey[j]; bx = sbox[j]; ar = sarea[j];
                    for (int t = 0; t < nk; t++) {
                        if (iou_pa(s_kbox[t], s_karea[t], bx, ar) > MAX_OVERLAP) {
                            ok = false; break;
                        }
                    }
                }
                unsigned b = __ballot_sync(0xffffffffu, ok);
                if (lane == 0) s_wcnt[wid] = __popc(b);
                __syncthreads();          // reads done; safe to write below
                int wpre = 0, wsum = 0;
                #pragma unroll
                for (int w = 0; w < NWARPS; w++) {
                    int cnt = s_wcnt[w];
                    if (w < wid) wpre += cnt;
                    wsum += cnt;
                }
                int rank = newbase + wpre + __popc(b & lmask);
                if (ok) { skey[rank] = key; sbox[rank] = bx; sarea[rank] = ar; }
                newbase += wsum;
                __syncthreads();
            }
            nrem = newbase;
        }
    }

    // pad unused candidate slots; publish kept count
    int kc = min(keptTotal, TOPK);
    for (int r = kc + tid; r < TOPK; r += NMS_NT)
        g_candScore[img][c][r] = -INFINITY;
    if (tid == 0) g_candCnt[img][c] = keptTotal;
}

// ---------------- kernel 3: per-image 20-way sorted merge top-200 ----------------
#define TKM_NT 256
__global__ void __launch_bounds__(TKM_NT, 1)
topk_merge_kernel(float* __restrict__ out)
{
    __shared__ float ssc[NCLS * TOPK];   // preloaded per-class sorted scores
    __shared__ float osc[TOPK];
    __shared__ int   ocls[TOPK];
    __shared__ int   orow[TOPK];
    __shared__ int   s_total, s_found;

    int img = blockIdx.x;
    int tid = threadIdx.x;

    const float* src = &g_candScore[img][0][0];
    for (int t = tid; t < NCLS * TOPK; t += TKM_NT)
        ssc[t] = src[t];
    if (tid == 0) {
        int tt = 0;
        for (int c = 0; c < NCLS; c++) tt += g_candCnt[img][c];
        s_total = tt;
        s_found = 0;
    }
    __syncthreads();

    if (tid < 32) {
        int lane = tid;
        int r = 0;
        float h = (lane < NCLS) ? ssc[lane * TOPK] : -INFINITY;
        int found = 0;
        for (int k = 0; k < TOPK; k++) {
            // order-preserving key: scores are >0 or -inf
            unsigned key = (h == -INFINITY) ? 0u
                         : (__float_as_uint(h) | 0x80000000u);
            unsigned mx = __reduce_max_sync(0xffffffffu, key);
            if (mx == 0u) break;                       // uniform
            unsigned tie = __ballot_sync(0xffffffffu, key == mx);
            int cwin = __ffs(tie) - 1;                 // smallest class wins tie
            if (lane == cwin) {
                osc[k]  = h;
                ocls[k] = cwin;
                orow[k] = r;
                r++;
                h = (r < TOPK) ? ssc[cwin * TOPK + r] : -INFINITY;
            }
            found = k + 1;
        }
        if (lane == 0) s_found = found;
    }
    __syncthreads();

    float* outBoxes  = out;                                     // [4,200,4]
    float* outLabels = out + NIMG * TOPK * 4;                   // [4,200]
    float* outScores = out + NIMG * TOPK * 4 + NIMG * TOPK;     // [4,200]
    float* outCount  = out + NIMG * TOPK * 4 + 2 * NIMG * TOPK; // [4]

    int found = s_found;
    for (int k = tid; k < TOPK; k += TKM_NT) {
        bool has = (k < found);
        float4 b = make_float4(0.f, 0.f, 0.f, 0.f);
        int lab = 0;
        float sc = 0.f;
        if (has) {
            b   = g_candBox[img][ocls[k]][orow[k]];
            lab = ocls[k] + 1;
            sc  = osc[k];
        }
        int basei = (img * TOPK + k) * 4;
        outBoxes[basei + 0] = b.x;
        outBoxes[basei + 1] = b.y;
        outBoxes[basei + 2] = b.z;
        outBoxes[basei + 3] = b.w;
        outLabels[img * TOPK + k] = (float)lab;
        outScores[img * TOPK + k] = sc;
    }
    __syncthreads();

    if (tid == 0) {
        int cnt = min(s_total, TOPK);
        if (cnt == 0) {
            int basei = img * TOPK * 4;
            outBoxes[basei + 0] = 0.0f;
            outBoxes[basei + 1] = 0.0f;
            outBoxes[basei + 2] = 1.0f;
            outBoxes[basei + 3] = 1.0f;
            cnt = 1;
        }
        outCount[img] = (float)cnt;
    }
}

// ---------------- launch ----------------
extern "C" void kernel_launch(void* const* d_in, const int* in_sizes, int n_in,
                              void* d_out, int out_size)
{
    const float* locs   = (const float*)d_in[0];  // (4,3106,4)
    const float* scores = (const float*)d_in[1];  // (4,3106,21)
    const float* priors = (const float*)d_in[2];  // (3106,4)
    float* out = (float*)d_out;

    static bool attr_set = false;
    if (!attr_set) {
        cudaFuncSetAttribute(nms_kernel,
                             cudaFuncAttributeMaxDynamicSharedMemorySize,
                             SMEM_NMS_BYTES);
        attr_set = true;
    }

    int rows = NIMG * NPRI;
    softmax_decode_kernel<<<(rows + 31) / 32, 32>>>(locs, scores, priors);
    nms_kernel<<<NIMG * NCLS, NMS_NT, SMEM_NMS_BYTES>>>();
    topk_merge_kernel<<<NIMG, TKM_NT>>>(out);
}

// round 8
// speedup vs baseline: 1.0502x; 1.0502x over previous
#include <cuda_runtime.h>
#include <math.h>
#include <limits.h>

#define NIMG 4
#define NPRI 3106
#define NCLS 20      // classes 1..20 (background excluded)
#define NTOT 21
#define NPAD 4096    // max pow2 bound for sort array
#define TOPK 200

#define MIN_SCORE 0.05f
#define MAX_OVERLAP 0.45f

#define NMS_NT 512
#define NWARPS (NMS_NT / 32)

// ---------------- device scratch (no allocations allowed) ----------------
__device__ float  g_cls[NIMG][NCLS][NPRI];      // class-major probs
__device__ float4 g_box[NIMG][NPRI];            // decoded boxes x1,y1,x2,y2
__device__ float  g_candScore[NIMG][NCLS][TOPK];
__device__ float4 g_candBox[NIMG][NCLS][TOPK];
__device__ int    g_candCnt[NIMG][NCLS];

// Fast double-precision exp (Cody-Waite + deg-12 Taylor, rel err ~2^-52).
__device__ __forceinline__ float exp_df(float xf)
{
    double x = (double)xf;
    float nf = rintf(xf * 1.4426950408889634f);
    double n = (double)nf;
    double r = fma(n, -0.6931471805599453, x);
    r = fma(n, -2.3190468138462996e-17, r);
    double p = 2.08767569878681e-09;
    p = fma(p, r, 2.505210838544172e-08);
    p = fma(p, r, 2.755731922398589e-07);
    p = fma(p, r, 2.755731922398589e-06);
    p = fma(p, r, 2.480158730158730e-05);
    p = fma(p, r, 1.984126984126984e-04);
    p = fma(p, r, 1.388888888888889e-03);
    p = fma(p, r, 8.333333333333333e-03);
    p = fma(p, r, 4.166666666666666e-02);
    p = fma(p, r, 1.666666666666667e-01);
    p = fma(p, r, 0.5);
    p = fma(p, r, 1.0);
    p = fma(p, r, 1.0);
    long long ni = (long long)nf;
    double sc = __longlong_as_double((ni + 1023LL) << 52);
    return (float)(p * sc);
}

// ---------------- kernel 1: softmax + box decode (WARP per row) ----------------
__global__ void softmax_decode_kernel(const float* __restrict__ locs,
                                      const float* __restrict__ scores,
                                      const float* __restrict__ priors)
{
    int gwarp = (blockIdx.x * blockDim.x + threadIdx.x) >> 5;
    int lane  = threadIdx.x & 31;
    if (gwarp >= NIMG * NPRI) return;
    int img = gwarp / NPRI;
    int p   = gwarp - img * NPRI;

    const float* s  = scores + (size_t)gwarp * NTOT;
    const float* l  = locs   + (size_t)gwarp * 4;
    const float* pr = priors + (size_t)p * 4;

    float z = (lane < NTOT) ? s[lane] : -INFINITY;

    float m = z;
    #pragma unroll
    for (int off = 16; off > 0; off >>= 1)
        m = fmaxf(m, __shfl_xor_sync(0xffffffffu, m, off));

    // one exp per lane (softmax) + decode exps on lanes 21/22 — all parallel
    float fe = 0.0f;
    if (lane < NTOT)      fe = exp_df(z - m);
    else if (lane == 21)  fe = exp_df(__fdiv_rn(l[2], 5.0f)) * pr[2];
    else if (lane == 22)  fe = exp_df(__fdiv_rn(l[3], 5.0f)) * pr[3];

    double ds = (lane < NTOT) ? (double)fe : 0.0;
    #pragma unroll
    for (int off = 16; off > 0; off >>= 1)
        ds += __shfl_xor_sync(0xffffffffu, ds, off);
    float fsum = (float)ds;

    if (lane >= 1 && lane < NTOT)
        g_cls[img][lane - 1][p] = __fdiv_rn(fe, fsum);

    float w = __shfl_sync(0xffffffffu, fe, 21);
    float h = __shfl_sync(0xffffffffu, fe, 22);
    if (lane == 0) {
        float cx = __fdiv_rn(l[0] * pr[2], 10.0f) + pr[0];
        float cy = __fdiv_rn(l[1] * pr[3], 10.0f) + pr[1];
        float4 b;
        b.x = cx - __fdiv_rn(w, 2.0f);
        b.y = cy - __fdiv_rn(h, 2.0f);
        b.z = cx + __fdiv_rn(w, 2.0f);
        b.w = cy + __fdiv_rn(h, 2.0f);
        g_box[img][p] = b;
    }
}

// IoU with precomputed areas; float semantics identical to reference
__device__ __forceinline__ float iou_pa(float4 a, float aA, float4 b, float aB)
{
    float dx = fminf(a.z, b.z) - fmaxf(a.x, b.x);
    float dy = fminf(a.w, b.w) - fmaxf(a.y, b.y);
    float inter = fmaxf(dx, 0.0f) * fmaxf(dy, 0.0f);
    return __fdiv_rn(inter, aA + aB - inter);
}

// ---------------- kernel 2: per-(image,class) greedy NMS ----------------
// Dynamic shared layout:
//   [0, 32768)       u64   skey64[NPAD]   (score_bits<<32 | ~idx)
//   [32768, 82464)   float4 sbox[NPRI]
//   [82464, 94888)   uint  omask[NPRI]
#define SMEM_NMS_BYTES 94976

__global__ void __launch_bounds__(NMS_NT, 1)
nms_kernel()
{
    extern __shared__ char sm[];
    unsigned long long* skey64 = (unsigned long long*)(sm);
    float4*             sbox   = (float4*)(sm + NPAD * 8);
    unsigned int*       omask  = (unsigned int*)(sm + NPAD * 8 + NPRI * 16);
    __shared__ int      s_wcnt[NWARPS];
    __shared__ unsigned s_keptmask;

    int img  = blockIdx.x / NCLS;
    int c    = blockIdx.x % NCLS;
    int tid  = threadIdx.x;
    int wid  = tid >> 5;
    int lane = tid & 31;
    unsigned lmask = (1u << lane) - 1u;

    // ---- Phase A: stable compaction of valid entries ----
    int base = 0;
    for (int bp = 0; bp < NPRI; bp += NMS_NT) {
        int p = bp + tid;
        float sc = (p < NPRI) ? g_cls[img][c][p] : 0.0f;
        bool ok = (p < NPRI) && (sc > MIN_SCORE);
        unsigned b = __ballot_sync(0xffffffffu, ok);
        if (lane == 0) s_wcnt[wid] = __popc(b);
        __syncthreads();
        int wpre = 0, wsum = 0;
        #pragma unroll
        for (int w = 0; w < NWARPS; w++) {
            int cnt = s_wcnt[w];
            if (w < wid) wpre += cnt;
            wsum += cnt;
        }
        int rank = base + wpre + __popc(b & lmask);
        if (ok)
            skey64[rank] = ((unsigned long long)__float_as_uint(sc) << 32)
                         | (unsigned int)(~p);
        base += wsum;
        __syncthreads();
    }
    int nvalid = base;

    int keptTotal = 0;

    if (nvalid > 0) {
        int npow = 32;
        while (npow < nvalid) npow <<= 1;
        for (int t = nvalid + tid; t < npow; t += NMS_NT)
            skey64[t] = 0ull;
        __syncthreads();

        // ---- Phase B: bitonic sort, descending u64 (score desc, idx asc) ----
        for (int k = 2; k <= npow; k <<= 1) {
            for (int j = k >> 1; j > 0; j >>= 1) {
                for (int t = tid; t < npow; t += NMS_NT) {
                    int l = t ^ j;
                    if (l > t) {
                        unsigned long long ka = skey64[t], kb = skey64[l];
                        bool asc = ((t & k) == 0);
                        if ((kb > ka) == asc) {
                            skey64[t] = kb;
                            skey64[l] = ka;
                        }
                    }
                }
                __syncthreads();
            }
        }

        // ---- Phase C: gather boxes for sorted valid positions ----
        for (int i = tid; i < nvalid; i += NMS_NT) {
            unsigned idx = ~((unsigned)skey64[i]);
            sbox[i] = g_box[img][idx];
        }
        __syncthreads();

        // ---- Phase D: chunked greedy; resolve || omask concurrent ----
        int nrem = nvalid;
        while (nrem > 0 && keptTotal < TOPK) {
            int m = min(32, nrem);

            if (wid == 0) {
                // warp 0: resolve chunk [0,m) greedily
                int li = (lane < m) ? lane : (m - 1);
                float4 bown = sbox[li];
                float  aown = (bown.z - bown.x) * (bown.w - bown.y);
                unsigned row = 0;   // bits j>lane that I overlap
                for (int j = 1; j < m; j++) {
                    float4 bj = sbox[j];          // LDS broadcast
                    float  aj = (bj.z - bj.x) * (bj.w - bj.y);
                    if (j > lane && iou_pa(bown, aown, bj, aj) > MAX_OVERLAP)
                        row |= 1u << j;
                }
                unsigned unres = (m == 32) ? 0xffffffffu : ((1u << m) - 1u);
                unsigned kept = 0;
                while (unres) {
                    int i = __ffs(unres) - 1;
                    kept |= 1u << i;
                    unsigned ri = __shfl_sync(0xffffffffu, row, i);
                    unres &= ~(ri | (1u << i));
                }
                bool mykept = (lane < m) && ((kept >> lane) & 1u);
                int myrank = __popc(kept & lmask);
                if (mykept) {
                    int slot = keptTotal + myrank;
                    if (slot < TOPK) {
                        g_candScore[img][c][slot] =
                            __uint_as_float((unsigned)(skey64[lane] >> 32));
                        g_candBox[img][c][slot] = bown;
                    }
                }
                if (lane == 0) s_keptmask = kept;
            } else {
                // warps 1..15: per-survivor overlap mask vs chunk (concurrent,
                // independent of which chunk members end up kept)
                for (int j = m + (tid - 32); j < nrem; j += (NMS_NT - 32)) {
                    float4 bj = sbox[j];
                    float  aj = (bj.z - bj.x) * (bj.w - bj.y);
                    unsigned om = 0;
                    for (int i = 0; i < m; i++) {
                        float4 bi = sbox[i];      // LDS broadcast
                        float  ai = (bi.z - bi.x) * (bi.w - bi.y);
                        if (iou_pa(bi, ai, bj, aj) > MAX_OVERLAP) om |= 1u << i;
                    }
                    omask[j] = om;
                }
            }
            __syncthreads();

            unsigned keptmask = s_keptmask;
            keptTotal += __popc(keptmask);
            if (keptTotal >= TOPK) break;
            if (nrem <= 32) { nrem = 0; break; }

            // stable compact survivors not overlapped by any kept chunk member
            int newbase = 0;
            for (int start = m; start < nrem; start += NMS_NT) {
                int j = start + tid;
                bool ok = (j < nrem) && ((omask[j] & keptmask) == 0u);
                unsigned long long key = 0ull; float4 bx;
                if (ok) { key = skey64[j]; bx = sbox[j]; }
                unsigned b = __ballot_sync(0xffffffffu, ok);
                if (lane == 0) s_wcnt[wid] = __popc(b);
                __syncthreads();          // reads done; safe to write
                int wpre = 0, wsum = 0;
                #pragma unroll
                for (int w = 0; w < NWARPS; w++) {
                    int cnt = s_wcnt[w];
                    if (w < wid) wpre += cnt;
                    wsum += cnt;
                }
                int rank = newbase + wpre + __popc(b & lmask);
                if (ok) { skey64[rank] = key; sbox[rank] = bx; }
                newbase += wsum;
                __syncthreads();
            }
            nrem = newbase;
        }
    }

    // pad unused candidate slots; publish kept count
    int kc = min(keptTotal, TOPK);
    for (int r = kc + tid; r < TOPK; r += NMS_NT)
        g_candScore[img][c][r] = -INFINITY;
    if (tid == 0) g_candCnt[img][c] = keptTotal;
}

// ---------------- kernel 3: per-image 20-way sorted merge top-200 ----------------
#define TKM_NT 256
__global__ void __launch_bounds__(TKM_NT, 1)
topk_merge_kernel(float* __restrict__ out)
{
    __shared__ float ssc[NCLS * TOPK];
    __shared__ float osc[TOPK];
    __shared__ int   ocls[TOPK];
    __shared__ int   orow[TOPK];
    __shared__ int   s_total, s_found;

    int img = blockIdx.x;
    int tid = threadIdx.x;

    const float* src = &g_candScore[img][0][0];
    for (int t = tid; t < NCLS * TOPK; t += TKM_NT)
        ssc[t] = src[t];
    if (tid == 0) {
        int tt = 0;
        for (int c = 0; c < NCLS; c++) tt += g_candCnt[img][c];
        s_total = tt;
        s_found = 0;
    }
    __syncthreads();

    if (tid < 32) {
        int lane = tid;
        int r = 0;
        float h = (lane < NCLS) ? ssc[lane * TOPK] : -INFINITY;
        int found = 0;
        for (int k = 0; k < TOPK; k++) {
            unsigned key = (h == -INFINITY) ? 0u
                         : (__float_as_uint(h) | 0x80000000u);
            unsigned mx = __reduce_max_sync(0xffffffffu, key);
            if (mx == 0u) break;
            unsigned tie = __ballot_sync(0xffffffffu, key == mx);
            int cwin = __ffs(tie) - 1;           // smallest class wins tie
            if (lane == cwin) {
                osc[k]  = h;
                ocls[k] = cwin;
                orow[k] = r;
                r++;
                h = (r < TOPK) ? ssc[cwin * TOPK + r] : -INFINITY;
            }
            found = k + 1;
        }
        if (lane == 0) s_found = found;
    }
    __syncthreads();

    float* outBoxes  = out;                                     // [4,200,4]
    float* outLabels = out + NIMG * TOPK * 4;                   // [4,200]
    float* outScores = out + NIMG * TOPK * 4 + NIMG * TOPK;     // [4,200]
    float* outCount  = out + NIMG * TOPK * 4 + 2 * NIMG * TOPK; // [4]

    int found = s_found;
    for (int k = tid; k < TOPK; k += TKM_NT) {
        bool has = (k < found);
        float4 b = make_float4(0.f, 0.f, 0.f, 0.f);
        int lab = 0;
        float sc = 0.f;
        if (has) {
            b   = g_candBox[img][ocls[k]][orow[k]];
            lab = ocls[k] + 1;
            sc  = osc[k];
        }
        int basei = (img * TOPK + k) * 4;
        outBoxes[basei + 0] = b.x;
        outBoxes[basei + 1] = b.y;
        outBoxes[basei + 2] = b.z;
        outBoxes[basei + 3] = b.w;
        outLabels[img * TOPK + k] = (float)lab;
        outScores[img * TOPK + k] = sc;
    }
    __syncthreads();

    if (tid == 0) {
        int cnt = min(s_total, TOPK);
        if (cnt == 0) {
            int basei = img * TOPK * 4;
            outBoxes[basei + 0] = 0.0f;
            outBoxes[basei + 1] = 0.0f;
            outBoxes[basei + 2] = 1.0f;
            outBoxes[basei + 3] = 1.0f;
            cnt = 1;
        }
        outCount[img] = (float)cnt;
    }
}

// ---------------- launch ----------------
extern "C" void kernel_launch(void* const* d_in, const int* in_sizes, int n_in,
                              void* d_out, int out_size)
{
    const float* locs   = (const float*)d_in[0];  // (4,3106,4)
    const float* scores = (const float*)d_in[1];  // (4,3106,21)
    const float* priors = (const float*)d_in[2];  // (3106,4)
    float* out = (float*)d_out;

    static bool attr_set = false;
    if (!attr_set) {
        cudaFuncSetAttribute(nms_kernel,
                             cudaFuncAttributeMaxDynamicSharedMemorySize,
                             SMEM_NMS_BYTES);
        attr_set = true;
    }

    int warps = NIMG * NPRI;                  // one warp per row
    int threads = 128;
    int blocks = (warps * 32 + threads - 1) / threads;
    softmax_decode_kernel<<<blocks, threads>>>(locs, scores, priors);
    nms_kernel<<<NIMG * NCLS, NMS_NT, SMEM_NMS_BYTES>>>();
    topk_merge_kernel<<<NIMG, TKM_NT>>>(out);
}

// round 9
// speedup vs baseline: 1.4404x; 1.3715x over previous
#include <cuda_runtime.h>
#include <math.h>
#include <limits.h>

#define NIMG 4
#define NPRI 3106
#define NCLS 20      // classes 1..20 (background excluded)
#define NTOT 21
#define NPAD 4096    // max pow2 bound for sort array
#define TOPK 200

#define MIN_SCORE 0.05f
#define MAX_OVERLAP 0.45f

#define NMS_NT 1024
#define NWARPS (NMS_NT / 32)   // 32

// ---------------- device scratch (no allocations allowed) ----------------
__device__ float  g_cls[NIMG][NCLS][NPRI];      // class-major probs
__device__ float4 g_box[NIMG][NPRI];            // decoded boxes x1,y1,x2,y2
__device__ float  g_candScore[NIMG][NCLS][TOPK];
__device__ float4 g_candBox[NIMG][NCLS][TOPK];
__device__ int    g_candCnt[NIMG][NCLS];

// Fast double-precision exp (Cody-Waite + deg-12 Taylor, rel err ~2^-52).
__device__ __forceinline__ float exp_df(float xf)
{
    double x = (double)xf;
    float nf = rintf(xf * 1.4426950408889634f);
    double n = (double)nf;
    double r = fma(n, -0.6931471805599453, x);
    r = fma(n, -2.3190468138462996e-17, r);
    double p = 2.08767569878681e-09;
    p = fma(p, r, 2.505210838544172e-08);
    p = fma(p, r, 2.755731922398589e-07);
    p = fma(p, r, 2.755731922398589e-06);
    p = fma(p, r, 2.480158730158730e-05);
    p = fma(p, r, 1.984126984126984e-04);
    p = fma(p, r, 1.388888888888889e-03);
    p = fma(p, r, 8.333333333333333e-03);
    p = fma(p, r, 4.166666666666666e-02);
    p = fma(p, r, 1.666666666666667e-01);
    p = fma(p, r, 0.5);
    p = fma(p, r, 1.0);
    p = fma(p, r, 1.0);
    long long ni = (long long)nf;
    double sc = __longlong_as_double((ni + 1023LL) << 52);
    return (float)(p * sc);
}

// ---------------- kernel 1: softmax + box decode (thread per row) ----------------
__global__ void softmax_decode_kernel(const float* __restrict__ locs,
                                      const float* __restrict__ scores,
                                      const float* __restrict__ priors)
{
    int row = blockIdx.x * blockDim.x + threadIdx.x;
    if (row >= NIMG * NPRI) return;
    int img = row / NPRI;
    int p   = row - img * NPRI;

    const float* s = scores + (size_t)row * NTOT;
    float m = s[0];
    #pragma unroll
    for (int c = 1; c < NTOT; c++) m = fmaxf(m, s[c]);

    float e[NTOT];
    double dsum = 0.0;
    #pragma unroll
    for (int c = 0; c < NTOT; c++) {
        e[c] = exp_df(s[c] - m);
        dsum += (double)e[c];
    }
    float fsum = (float)dsum;
    #pragma unroll
    for (int c = 1; c < NTOT; c++)
        g_cls[img][c - 1][p] = __fdiv_rn(e[c], fsum);

    const float* l  = locs + (size_t)row * 4;
    const float* pr = priors + (size_t)p * 4;
    float cx = __fdiv_rn(l[0] * pr[2], 10.0f) + pr[0];
    float cy = __fdiv_rn(l[1] * pr[3], 10.0f) + pr[1];
    float w  = exp_df(__fdiv_rn(l[2], 5.0f)) * pr[2];
    float h  = exp_df(__fdiv_rn(l[3], 5.0f)) * pr[3];
    float4 b;
    b.x = cx - __fdiv_rn(w, 2.0f);
    b.y = cy - __fdiv_rn(h, 2.0f);
    b.z = cx + __fdiv_rn(w, 2.0f);
    b.w = cy + __fdiv_rn(h, 2.0f);
    g_box[img][p] = b;
}

// IoU with precomputed areas; float semantics identical to reference
__device__ __forceinline__ float iou_pa(float4 a, float aA, float4 b, float aB)
{
    float dx = fminf(a.z, b.z) - fmaxf(a.x, b.x);
    float dy = fminf(a.w, b.w) - fmaxf(a.y, b.y);
    float inter = fmaxf(dx, 0.0f) * fmaxf(dy, 0.0f);
    return __fdiv_rn(inter, aA + aB - inter);
}

// exclusive warp-count prefix via shfl scan; s_wcnt[lane] must be valid for
// lane < NWARPS (NWARPS == 32). Returns {wpre, wsum} for this thread's wid.
__device__ __forceinline__ void scan_counts(const int* s_wcnt, int wid, int lane,
                                            int& wpre, int& wsum)
{
    int x = s_wcnt[lane];
    #pragma unroll
    for (int d = 1; d < 32; d <<= 1) {
        int v = __shfl_up_sync(0xffffffffu, x, d);
        if (lane >= d) x += v;
    }
    wsum = __shfl_sync(0xffffffffu, x, 31);
    wpre = (wid == 0) ? 0 : __shfl_sync(0xffffffffu, x, wid - 1);
}

// ---------------- kernel 2: per-(image,class) greedy NMS ----------------
// Dynamic shared layout:
//   [0, 32768)       u64   skey64[NPAD]   (score_bits<<32 | ~idx)
//   [32768, 82464)   float4 sbox[NPRI]
//   [82464, 94888)   uint  omask[NPRI]
#define SMEM_NMS_BYTES 94976

__global__ void __launch_bounds__(NMS_NT, 1)
nms_kernel()
{
    extern __shared__ char sm[];
    unsigned long long* skey64 = (unsigned long long*)(sm);
    float4*             sbox   = (float4*)(sm + NPAD * 8);
    unsigned int*       omask  = (unsigned int*)(sm + NPAD * 8 + NPRI * 16);
    __shared__ int      s_wcnt[NWARPS];
    __shared__ unsigned s_keptmask;

    int img  = blockIdx.x / NCLS;
    int c    = blockIdx.x % NCLS;
    int tid  = threadIdx.x;
    int wid  = tid >> 5;
    int lane = tid & 31;
    unsigned lmask = (1u << lane) - 1u;

    // ---- Phase A: stable compaction of valid entries ----
    int base = 0;
    for (int bp = 0; bp < NPRI; bp += NMS_NT) {
        int p = bp + tid;
        float sc = (p < NPRI) ? g_cls[img][c][p] : 0.0f;
        bool ok = (p < NPRI) && (sc > MIN_SCORE);
        unsigned b = __ballot_sync(0xffffffffu, ok);
        if (lane == 0) s_wcnt[wid] = __popc(b);
        __syncthreads();
        int wpre, wsum;
        scan_counts(s_wcnt, wid, lane, wpre, wsum);
        int rank = base + wpre + __popc(b & lmask);
        if (ok)
            skey64[rank] = ((unsigned long long)__float_as_uint(sc) << 32)
                         | (unsigned int)(~p);
        base += wsum;
        __syncthreads();
    }
    int nvalid = base;

    int keptTotal = 0;

    if (nvalid > 0) {
        int npow = 32;
        while (npow < nvalid) npow <<= 1;
        for (int t = nvalid + tid; t < npow; t += NMS_NT)
            skey64[t] = 0ull;
        __syncthreads();

        // ---- Phase B: bitonic sort, descending u64 (score desc, idx asc) ----
        for (int k = 2; k <= npow; k <<= 1) {
            for (int j = k >> 1; j > 0; j >>= 1) {
                for (int t = tid; t < npow; t += NMS_NT) {
                    int l = t ^ j;
                    if (l > t) {
                        unsigned long long ka = skey64[t], kb = skey64[l];
                        bool asc = ((t & k) == 0);
                        if ((kb > ka) == asc) {
                            skey64[t] = kb;
                            skey64[l] = ka;
                        }
                    }
                }
                __syncthreads();
            }
        }

        // ---- Phase C: gather boxes for sorted valid positions ----
        for (int i = tid; i < nvalid; i += NMS_NT) {
            unsigned idx = ~((unsigned)skey64[i]);
            sbox[i] = g_box[img][idx];
        }
        __syncthreads();

        // ---- Phase D: chunked greedy; warp0 resolve || warps1-31 omask ----
        int nrem = nvalid;
        while (nrem > 0 && keptTotal < TOPK) {
            int m = min(32, nrem);

            if (wid == 0) {
                // warp 0: resolve chunk [0,m) greedily
                int li = (lane < m) ? lane : (m - 1);
                float4 bown = sbox[li];
                float  aown = (bown.z - bown.x) * (bown.w - bown.y);
                unsigned row = 0;   // bits j>lane that I overlap
                for (int j = 1; j < m; j++) {
                    float4 bj = sbox[j];          // LDS broadcast
                    float  aj = (bj.z - bj.x) * (bj.w - bj.y);
                    if (j > lane && iou_pa(bown, aown, bj, aj) > MAX_OVERLAP)
                        row |= 1u << j;
                }
                unsigned unres = (m == 32) ? 0xffffffffu : ((1u << m) - 1u);
                unsigned kept = 0;
                while (unres) {
                    int i = __ffs(unres) - 1;
                    kept |= 1u << i;
                    unsigned ri = __shfl_sync(0xffffffffu, row, i);
                    unres &= ~(ri | (1u << i));
                }
                bool mykept = (lane < m) && ((kept >> lane) & 1u);
                int myrank = __popc(kept & lmask);
                if (mykept) {
                    int slot = keptTotal + myrank;
                    if (slot < TOPK) {
                        g_candScore[img][c][slot] =
                            __uint_as_float((unsigned)(skey64[lane] >> 32));
                        g_candBox[img][c][slot] = bown;
                    }
                }
                if (lane == 0) s_keptmask = kept;
            } else {
                // warps 1..31: per-survivor overlap mask vs chunk (concurrent,
                // independent of which chunk members end up kept)
                for (int j = m + (tid - 32); j < nrem; j += (NMS_NT - 32)) {
                    float4 bj = sbox[j];
                    float  aj = (bj.z - bj.x) * (bj.w - bj.y);
                    unsigned om = 0;
                    for (int i = 0; i < m; i++) {
                        float4 bi = sbox[i];      // LDS broadcast
                        float  ai = (bi.z - bi.x) * (bi.w - bi.y);
                        if (iou_pa(bi, ai, bj, aj) > MAX_OVERLAP) om |= 1u << i;
                    }
                    omask[j] = om;
                }
            }
            __syncthreads();

            unsigned keptmask = s_keptmask;
            keptTotal += __popc(keptmask);
            if (keptTotal >= TOPK) break;
            if (nrem <= 32) { nrem = 0; break; }

            // stable compact survivors not overlapped by any kept chunk member
            int newbase = 0;
            for (int start = m; start < nrem; start += NMS_NT) {
                int j = start + tid;
                bool ok = (j < nrem) && ((omask[j] & keptmask) == 0u);
                unsigned long long key = 0ull; float4 bx;
                if (ok) { key = skey64[j]; bx = sbox[j]; }
                unsigned b = __ballot_sync(0xffffffffu, ok);
                if (lane == 0) s_wcnt[wid] = __popc(b);
                __syncthreads();          // reads done; safe to write
                int wpre, wsum;
                scan_counts(s_wcnt, wid, lane, wpre, wsum);
                int rank = newbase + wpre + __popc(b & lmask);
                if (ok) { skey64[rank] = key; sbox[rank] = bx; }
                newbase += wsum;
                __syncthreads();
            }
            nrem = newbase;
        }
    }

    // pad unused candidate slots; publish kept count
    int kc = min(keptTotal, TOPK);
    for (int r = kc + tid; r < TOPK; r += NMS_NT)
        g_candScore[img][c][r] = -INFINITY;
    if (tid == 0) g_candCnt[img][c] = keptTotal;
}

// ---------------- kernel 3: per-image 20-way sorted merge top-200 ----------------
#define TKM_NT 256
__global__ void __launch_bounds__(TKM_NT, 1)
topk_merge_kernel(float* __restrict__ out)
{
    __shared__ float ssc[NCLS * TOPK];
    __shared__ float osc[TOPK];
    __shared__ int   ocls[TOPK];
    __shared__ int   orow[TOPK];
    __shared__ int   s_total, s_found;

    int img = blockIdx.x;
    int tid = threadIdx.x;

    const float* src = &g_candScore[img][0][0];
    for (int t = tid; t < NCLS * TOPK; t += TKM_NT)
        ssc[t] = src[t];
    if (tid == 0) {
        int tt = 0;
        for (int c = 0; c < NCLS; c++) tt += g_candCnt[img][c];
        s_total = tt;
        s_found = 0;
    }
    __syncthreads();

    if (tid < 32) {
        int lane = tid;
        int r = 0;
        float h = (lane < NCLS) ? ssc[lane * TOPK] : -INFINITY;
        int found = 0;
        for (int k = 0; k < TOPK; k++) {
            unsigned key = (h == -INFINITY) ? 0u
                         : (__float_as_uint(h) | 0x80000000u);
            unsigned mx = __reduce_max_sync(0xffffffffu, key);
            if (mx == 0u) break;
            unsigned tie = __ballot_sync(0xffffffffu, key == mx);
            int cwin = __ffs(tie) - 1;           // smallest class wins tie
            if (lane == cwin) {
                osc[k]  = h;
                ocls[k] = cwin;
                orow[k] = r;
                r++;
                h = (r < TOPK) ? ssc[cwin * TOPK + r] : -INFINITY;
            }
            found = k + 1;
        }
        if (lane == 0) s_found = found;
    }
    __syncthreads();

    float* outBoxes  = out;                                     // [4,200,4]
    float* outLabels = out + NIMG * TOPK * 4;                   // [4,200]
    float* outScores = out + NIMG * TOPK * 4 + NIMG * TOPK;     // [4,200]
    float* outCount  = out + NIMG * TOPK * 4 + 2 * NIMG * TOPK; // [4]

    int found = s_found;
    for (int k = tid; k < TOPK; k += TKM_NT) {
        bool has = (k < found);
        float4 b = make_float4(0.f, 0.f, 0.f, 0.f);
        int lab = 0;
        float sc = 0.f;
        if (has) {
            b   = g_candBox[img][ocls[k]][orow[k]];
            lab = ocls[k] + 1;
            sc  = osc[k];
        }
        int basei = (img * TOPK + k) * 4;
        outBoxes[basei + 0] = b.x;
        outBoxes[basei + 1] = b.y;
        outBoxes[basei + 2] = b.z;
        outBoxes[basei + 3] = b.w;
        outLabels[img * TOPK + k] = (float)lab;
        outScores[img * TOPK + k] = sc;
    }
    __syncthreads();

    if (tid == 0) {
        int cnt = min(s_total, TOPK);
        if (cnt == 0) {
            int basei = img * TOPK * 4;
            outBoxes[basei + 0] = 0.0f;
            outBoxes[basei + 1] = 0.0f;
            outBoxes[basei + 2] = 1.0f;
            outBoxes[basei + 3] = 1.0f;
            cnt = 1;
        }
        outCount[img] = (float)cnt;
    }
}

// ---------------- launch ----------------
extern "C" void kernel_launch(void* const* d_in, const int* in_sizes, int n_in,
                              void* d_out, int out_size)
{
    const float* locs   = (const float*)d_in[0];  // (4,3106,4)
    const float* scores = (const float*)d_in[1];  // (4,3106,21)
    const float* priors = (const float*)d_in[2];  // (3106,4)
    float* out = (float*)d_out;

    static bool attr_set = false;
    if (!attr_set) {
        cudaFuncSetAttribute(nms_kernel,
                             cudaFuncAttributeMaxDynamicSharedMemorySize,
                             SMEM_NMS_BYTES);
        attr_set = true;
    }

    int rows = NIMG * NPRI;
    softmax_decode_kernel<<<(rows + 31) / 32, 32>>>(locs, scores, priors);
    nms_kernel<<<NIMG * NCLS, NMS_NT, SMEM_NMS_BYTES>>>();
    topk_merge_kernel<<<NIMG, TKM_NT>>>(out);
}